// round 5
// baseline (speedup 1.0000x reference)
#include <cuda_runtime.h>
#include <math.h>

#define N    2708
#define INC  1433
#define OC   128
#define NCH  32
#define RC   85      // ceil(N/NCH)
#define RPB  16
#define JT   64
#define NW4  677     // N/4 exactly (2708 = 677*4)

// ---------------- scratch (static device memory) -----------------------------
__device__ float  g_Kp[2][N * OC];      // K-split partials
__device__ float  g_K[N * OC];
__device__ float  g_k1[N], g_k2[N];
__device__ double g_part1[NCH * N], g_part2[NCH * N];
__device__ float  g_s1[N], g_s2[N];
__device__ float  g_p[N], g_q[N];

// ---------------- K = X @ W^T  (BM=32, BN=64, BK=16, 128 thr, 4x4 tile,
//                  z-split over K into 2 halves) -----------------------------
__global__ void gemm_k(const float* __restrict__ X, const float* __restrict__ W) {
    const int BM = 32, BN = 64, BK = 16;
    __shared__ float Xs[BK][36];   // stride 36 (mult of 4 for float4 reads)
    __shared__ float Ws[BK][68];
    int i0 = blockIdx.y * BM;
    int c0 = blockIdx.x * BN;
    int z  = blockIdx.z;
    int kb = z * 720;
    int ke = (z == 0) ? 720 : INC;
    int t  = threadIdx.x;
    int ty = t >> 4;    // 0..7 -> rows 4ty..4ty+3
    int tx = t & 15;    // 0..15 -> cols 4tx..4tx+3
    float acc[4][4] = {};
    for (int kt = kb; kt < ke; kt += BK) {
#pragma unroll
        for (int l = 0; l < 4; l++) {
            int e = t + l * 128;
            int r = e >> 4, kk = e & 15;
            int gi = i0 + r, gk = kt + kk;
            Xs[kk][r] = (gi < N && gk < ke) ? X[(size_t)gi * INC + gk] : 0.f;
        }
#pragma unroll
        for (int l = 0; l < 8; l++) {
            int e = t + l * 128;
            int c = e >> 4, kk = e & 15;
            int gk = kt + kk;
            Ws[kk][c] = (gk < ke) ? W[(size_t)(c0 + c) * INC + gk] : 0.f;
        }
        __syncthreads();
#pragma unroll
        for (int kk = 0; kk < BK; kk++) {
            float4 a = *(const float4*)&Xs[kk][4 * ty];
            float4 b = *(const float4*)&Ws[kk][4 * tx];
            acc[0][0] += a.x * b.x; acc[0][1] += a.x * b.y; acc[0][2] += a.x * b.z; acc[0][3] += a.x * b.w;
            acc[1][0] += a.y * b.x; acc[1][1] += a.y * b.y; acc[1][2] += a.y * b.z; acc[1][3] += a.y * b.w;
            acc[2][0] += a.z * b.x; acc[2][1] += a.z * b.y; acc[2][2] += a.z * b.z; acc[2][3] += a.z * b.w;
            acc[3][0] += a.w * b.x; acc[3][1] += a.w * b.y; acc[3][2] += a.w * b.z; acc[3][3] += a.w * b.w;
        }
        __syncthreads();
    }
#pragma unroll
    for (int rr = 0; rr < 4; rr++) {
        int gi = i0 + 4 * ty + rr;
        if (gi < N) {
            float4 v = make_float4(acc[rr][0], acc[rr][1], acc[rr][2], acc[rr][3]);
            *(float4*)&g_Kp[z][(size_t)gi * OC + c0 + 4 * tx] = v;
        }
    }
}

// ---------------- fold K halves + k1,k2 (double accum, one warp/row) --------
__global__ void fold_k1k2(const float* __restrict__ a1, const float* __restrict__ a2) {
    int w = threadIdx.x >> 5;
    int lane = threadIdx.x & 31;
    int i = blockIdx.x * 8 + w;
    if (i >= N) return;
    double d1 = 0.0, d2 = 0.0;
#pragma unroll
    for (int u = 0; u < 4; u++) {
        int c = lane + 32 * u;
        float kv = g_Kp[0][(size_t)i * OC + c] + g_Kp[1][(size_t)i * OC + c];
        g_K[(size_t)i * OC + c] = kv;
        d1 += (double)kv * (double)a1[c];
        d2 += (double)kv * (double)a2[c];
    }
#pragma unroll
    for (int off = 16; off; off >>= 1) {
        d1 += __shfl_down_sync(0xffffffffu, d1, off);
        d2 += __shfl_down_sync(0xffffffffu, d2, off);
    }
    if (lane == 0) { g_k1[i] = (float)d1; g_k2[i] = (float)d2; }
}

// ---------------- column partials: t1 = U^T k1, t2 = U^T 1 (double) ---------
__global__ void colpart(const float* __restrict__ U) {
    int j  = blockIdx.x * 256 + threadIdx.x;
    int ch = blockIdx.y;
    if (j >= N) return;
    int ib = ch * RC;
    int ie = min(N, ib + RC);
    double a = 0.0, b = 0.0;
    for (int i = ib; i < ie; i++) {
        float u = U[(size_t)i * N + j];
        a += (double)u * (double)g_k1[i];
        b += (double)u;
    }
    g_part1[ch * N + j] = a;
    g_part2[ch * N + j] = b;
}

// ---------------- s = lmbd * t  (double reduce) ------------------------------
__global__ void colreduce(const float* __restrict__ lmbd) {
    int j = blockIdx.x * 256 + threadIdx.x;
    if (j >= N) return;
    double a = 0.0, b = 0.0;
#pragma unroll
    for (int c = 0; c < NCH; c++) {
        a += g_part1[c * N + j];
        b += g_part2[c * N + j];
    }
    double l = (double)lmbd[j];
    g_s1[j] = (float)(l * a);
    g_s2[j] = (float)(l * b);
}

// ---------------- p = U s1, q = U s2 (double accum, float4 loads) -----------
__global__ void pq_kernel(const float* __restrict__ U) {
    __shared__ double r1[256], r2[256];
    int i = blockIdx.x;
    int t = threadIdx.x;
    double a = 0.0, b = 0.0;
    const float4* Ur = (const float4*)(U + (size_t)i * N);
    for (int j4 = t; j4 < NW4; j4 += 256) {
        float4 u = Ur[j4];
        int j = 4 * j4;
        a += (double)u.x * g_s1[j]   + (double)u.y * g_s1[j+1]
           + (double)u.z * g_s1[j+2] + (double)u.w * g_s1[j+3];
        b += (double)u.x * g_s2[j]   + (double)u.y * g_s2[j+1]
           + (double)u.z * g_s2[j+2] + (double)u.w * g_s2[j+3];
    }
    r1[t] = a; r2[t] = b;
    __syncthreads();
    for (int s = 128; s; s >>= 1) {
        if (t < s) { r1[t] += r1[t + s]; r2[t] += r2[t + s]; }
        __syncthreads();
    }
    if (t == 0) { g_p[i] = (float)r1[0]; g_q[i] = (float)r2[0]; }
}

// ---------------- fused: masked-softmax stats + H = alpha @ K ---------------
// Pass A: read A once, build bitmask in smem, online (m,l) per row.
// Pass B: weights from bitmask + stats, 16x128 accumulation with smem K tiles.
__global__ void attn_fused(const int* __restrict__ A, float* __restrict__ H) {
    __shared__ unsigned msk[RPB][88];        // 85 words used per row (5.6KB)
    __shared__ float4   Ksh[JT * 32];        // 64 j x 128 cols (32KB)
    __shared__ float    wsh[JT][16];         // transposed weights (4KB)
    __shared__ float    pm[RPB], qm[RPB], mm[RPB], lm[RPB];
    __shared__ float2   red[256];

    int i0 = blockIdx.x * RPB;
    int t  = threadIdx.x;
    int r  = t >> 4;        // row 0..15
    int l16 = t & 15;       // 16 threads per row
    int gi = i0 + r;

    // ---------- Pass A: mask + online (m, l) --------------------------------
    float m = -INFINITY, lsum = 0.f;
    if (gi < N) {
        float pr = g_p[gi], qr = g_q[gi];
        const int* Arow = A + (size_t)gi * N;
        for (int w = l16; w < 85; w += 16) {
            unsigned bits = 0;
            int jb = w * 32;
            const int4* Ap = (const int4*)(Arow + jb);
#pragma unroll
            for (int q4 = 0; q4 < 8; q4++) {
                int j = jb + 4 * q4;
                if (j >= N) break;
                int4 av = Ap[q4];
#define PROC(v, jj_)                                                       \
                if (v) {                                                   \
                    float x = fabsf(pr + qr * __ldg(&g_k2[jj_]));          \
                    bits |= 1u << ((jj_) - jb);                            \
                    if (x > m) { lsum = lsum * __expf(m - x) + 1.f; m = x; } \
                    else       { lsum += __expf(x - m); }                  \
                }
                PROC(av.x, j + 0)
                PROC(av.y, j + 1)
                PROC(av.z, j + 2)
                PROC(av.w, j + 3)
#undef PROC
            }
            msk[r][w] = bits;
        }
    } else {
        for (int w = l16; w < 85; w += 16) msk[r][w] = 0;
    }
    red[t] = make_float2(m, lsum);
    __syncthreads();
    if (t < RPB) {
        float M = -INFINITY, L = 0.f;
#pragma unroll
        for (int k = 0; k < 16; k++) M = fmaxf(M, red[t * 16 + k].x);
#pragma unroll
        for (int k = 0; k < 16; k++) {
            float2 v = red[t * 16 + k];
            if (v.y > 0.f) L += v.y * __expf(v.x - M);
        }
        int gir = i0 + t;
        pm[t] = (gir < N) ? g_p[gir] : 0.f;
        qm[t] = (gir < N) ? g_q[gir] : 0.f;
        mm[t] = M;
        lm[t] = (L > 0.f) ? 1.f / L : 0.f;
    }
    __syncthreads();

    // ---------- Pass B: H = alpha @ K ---------------------------------------
    int cg = t & 31;    // float4 col group
    int rg = t >> 5;    // warp id -> rows 2rg, 2rg+1
    float4 acc0 = make_float4(0.f, 0.f, 0.f, 0.f);
    float4 acc1 = make_float4(0.f, 0.f, 0.f, 0.f);

    for (int j0 = 0; j0 < N; j0 += JT) {
        // stage K tile
#pragma unroll
        for (int lq = 0; lq < 8; lq++) {
            int e = t + lq * 256;
            int jj = e >> 5, c4 = e & 31;
            int gj = j0 + jj;
            Ksh[jj * 32 + c4] = (gj < N) ? ((const float4*)g_K)[(size_t)gj * 32 + c4]
                                         : make_float4(0.f, 0.f, 0.f, 0.f);
        }
        // weights from bitmask (transposed layout)
#pragma unroll
        for (int lq = 0; lq < 4; lq++) {
            int e = t + lq * 256;
            int jj = e >> 4, rr = e & 15;
            int gj = j0 + jj;
            float wv = 0.f;
            if (gj < N && ((msk[rr][gj >> 5] >> (gj & 31)) & 1u))
                wv = __expf(fabsf(pm[rr] + qm[rr] * __ldg(&g_k2[gj])) - mm[rr]) * lm[rr];
            wsh[jj][rr] = wv;
        }
        __syncthreads();
#pragma unroll 4
        for (int jj = 0; jj < JT; jj++) {
            float4 kv = Ksh[jj * 32 + cg];
            float2 wv = *(const float2*)&wsh[jj][2 * rg];
            acc0.x += wv.x * kv.x; acc0.y += wv.x * kv.y; acc0.z += wv.x * kv.z; acc0.w += wv.x * kv.w;
            acc1.x += wv.y * kv.x; acc1.y += wv.y * kv.y; acc1.z += wv.y * kv.z; acc1.w += wv.y * kv.w;
        }
        __syncthreads();
    }
    int r0 = i0 + 2 * rg;
    if (r0 < N)     ((float4*)H)[(size_t)r0 * 32 + cg]       = acc0;
    if (r0 + 1 < N) ((float4*)H)[(size_t)(r0 + 1) * 32 + cg] = acc1;
}

// ---------------- launch -----------------------------------------------------
extern "C" void kernel_launch(void* const* d_in, const int* in_sizes, int n_in,
                              void* d_out, int out_size) {
    (void)in_sizes; (void)n_in; (void)out_size;
    const float* X    = (const float*)d_in[0];
    const int*   A    = (const int*)d_in[1];
    const float* U    = (const float*)d_in[2];
    const float* W    = (const float*)d_in[3];
    const float* a1   = (const float*)d_in[4];
    const float* a2   = (const float*)d_in[5];
    const float* lmbd = (const float*)d_in[6];
    float* H = (float*)d_out;

    gemm_k    <<<dim3(2, (N + 31) / 32, 2), 128>>>(X, W);
    fold_k1k2 <<<(N + 7) / 8, 256>>>(a1, a2);
    colpart   <<<dim3((N + 255) / 256, NCH), 256>>>(U);
    colreduce <<<(N + 255) / 256, 256>>>(lmbd);
    pq_kernel <<<N, 256>>>(U);
    attn_fused<<<(N + RPB - 1) / RPB, 256>>>(A, H);
}

// round 6
// speedup vs baseline: 1.1866x; 1.1866x over previous
#include <cuda_runtime.h>
#include <math.h>

#define N    2708
#define INC  1433
#define OC   128
#define NCH  32
#define RC   85      // ceil(N/NCH)
#define RPB  16
#define JT   64
#define NW4  677     // N/4 exactly

// ---------------- scratch (static device memory) -----------------------------
__device__ float g_K[N * OC];
__device__ float g_k1[N], g_k2[N];
__device__ float g_part1[NCH * N], g_part2[NCH * N];
__device__ float g_s1[N], g_s2[N];
__device__ float g_p[N], g_q[N];
__device__ float g_m[N], g_linv[N];

// ---------------- K = X @ W^T --------------------------------------------------
// BM=16, BN=64, BK=16, 128 threads, per-thread 2x4 (float4 B, broadcast A).
// Grid (2 col-tiles, 170 row-tiles) = 340 blocks -> balanced 2.3 waves.
__global__ void gemm_k(const float* __restrict__ X, const float* __restrict__ W) {
    __shared__ float Xs[16][17];   // [kk][row], stride 17 (conflict-free transpose)
    __shared__ float Ws[16][68];   // [kk][col], stride 68 (16B-aligned rows)
    int i0 = blockIdx.y * 16;
    int c0 = blockIdx.x * 64;
    int t  = threadIdx.x;
    int tx = t & 15;    // cols 4tx..4tx+3
    int ty = t >> 4;    // rows 2ty, 2ty+1
    float acc[2][4] = {};
    for (int kt = 0; kt < INC; kt += 16) {
#pragma unroll
        for (int l = 0; l < 2; l++) {
            int e = t + l * 128;
            int kk = e & 15, r = e >> 4;
            int gi = i0 + r, gk = kt + kk;
            Xs[kk][r] = (gi < N && gk < INC) ? X[(size_t)gi * INC + gk] : 0.f;
        }
#pragma unroll
        for (int l = 0; l < 8; l++) {
            int e = t + l * 128;
            int kk = e & 15, c = e >> 4;
            int gk = kt + kk;
            Ws[kk][c] = (gk < INC) ? W[(size_t)(c0 + c) * INC + gk] : 0.f;
        }
        __syncthreads();
#pragma unroll
        for (int kk = 0; kk < 16; kk++) {
            float a0 = Xs[kk][2 * ty];
            float a1 = Xs[kk][2 * ty + 1];
            float4 b = *(const float4*)&Ws[kk][4 * tx];
            acc[0][0] += a0 * b.x; acc[0][1] += a0 * b.y; acc[0][2] += a0 * b.z; acc[0][3] += a0 * b.w;
            acc[1][0] += a1 * b.x; acc[1][1] += a1 * b.y; acc[1][2] += a1 * b.z; acc[1][3] += a1 * b.w;
        }
        __syncthreads();
    }
#pragma unroll
    for (int rr = 0; rr < 2; rr++) {
        int gi = i0 + 2 * ty + rr;
        if (gi < N) {
            float4 v = make_float4(acc[rr][0], acc[rr][1], acc[rr][2], acc[rr][3]);
            *(float4*)&g_K[(size_t)gi * OC + c0 + 4 * tx] = v;
        }
    }
}

// ---------------- k1 = K a1^T, k2 = K a2^T (one warp per row) ---------------
__global__ void k1k2_kernel(const float* __restrict__ a1, const float* __restrict__ a2) {
    int w = threadIdx.x >> 5;
    int lane = threadIdx.x & 31;
    int i = blockIdx.x * 8 + w;
    if (i >= N) return;
    float d1 = 0.f, d2 = 0.f;
#pragma unroll
    for (int u = 0; u < 4; u++) {
        int c = lane + 32 * u;
        float kv = g_K[(size_t)i * OC + c];
        d1 += kv * a1[c];
        d2 += kv * a2[c];
    }
#pragma unroll
    for (int off = 16; off; off >>= 1) {
        d1 += __shfl_down_sync(0xffffffffu, d1, off);
        d2 += __shfl_down_sync(0xffffffffu, d2, off);
    }
    if (lane == 0) { g_k1[i] = d1; g_k2[i] = d2; }
}

// ---------------- column partials: t1 = U^T k1, t2 = U^T 1 -------------------
__global__ void colpart(const float* __restrict__ U) {
    int j  = blockIdx.x * 256 + threadIdx.x;
    int ch = blockIdx.y;
    if (j >= N) return;
    int ib = ch * RC;
    int ie = min(N, ib + RC);
    float a = 0.f, b = 0.f;
    for (int i = ib; i < ie; i++) {
        float u = U[(size_t)i * N + j];
        a += u * g_k1[i];
        b += u;
    }
    g_part1[ch * N + j] = a;
    g_part2[ch * N + j] = b;
}

// ---------------- s = lmbd * t  (fixed-order chunk reduce) -------------------
__global__ void colreduce(const float* __restrict__ lmbd) {
    int j = blockIdx.x * 256 + threadIdx.x;
    if (j >= N) return;
    float a = 0.f, b = 0.f;
#pragma unroll
    for (int c = 0; c < NCH; c++) {
        a += g_part1[c * N + j];
        b += g_part2[c * N + j];
    }
    float l = lmbd[j];
    g_s1[j] = l * a;
    g_s2[j] = l * b;
}

// ---------------- p = U s1, q = U s2 (float4 loads) --------------------------
__global__ void pq_kernel(const float* __restrict__ U) {
    __shared__ float r1[256], r2[256];
    int i = blockIdx.x;
    int t = threadIdx.x;
    float a = 0.f, b = 0.f;
    const float4* Ur = (const float4*)(U + (size_t)i * N);
    for (int j4 = t; j4 < NW4; j4 += 256) {
        float4 u = Ur[j4];
        int j = 4 * j4;
        a += u.x * g_s1[j] + u.y * g_s1[j + 1] + u.z * g_s1[j + 2] + u.w * g_s1[j + 3];
        b += u.x * g_s2[j] + u.y * g_s2[j + 1] + u.z * g_s2[j + 2] + u.w * g_s2[j + 3];
    }
    r1[t] = a; r2[t] = b;
    __syncthreads();
    for (int s = 128; s; s >>= 1) {
        if (t < s) { r1[t] += r1[t + s]; r2[t] += r2[t + s]; }
        __syncthreads();
    }
    if (t == 0) { g_p[i] = r1[0]; g_q[i] = r2[0]; }
}

// ---------------- per-row masked softmax stats: m_i, 1/l_i -------------------
__global__ void stats_kernel(const int* __restrict__ A) {
    __shared__ float red[256];
    int i = blockIdx.x, t = threadIdx.x;
    float pi = g_p[i], qi = g_q[i];
    const int* Arow = A + (size_t)i * N;
    float mx = -INFINITY;
    for (int j = t; j < N; j += 256)
        if (Arow[j]) mx = fmaxf(mx, fabsf(pi + qi * g_k2[j]));
    red[t] = mx;
    __syncthreads();
    for (int s = 128; s; s >>= 1) {
        if (t < s) red[t] = fmaxf(red[t], red[t + s]);
        __syncthreads();
    }
    float m = red[0];
    __syncthreads();
    float sum = 0.f;
    for (int j = t; j < N; j += 256)
        if (Arow[j]) sum += __expf(fabsf(pi + qi * g_k2[j]) - m);
    red[t] = sum;
    __syncthreads();
    for (int s = 128; s; s >>= 1) {
        if (t < s) red[t] += red[t + s];
        __syncthreads();
    }
    if (t == 0) { g_m[i] = m; g_linv[i] = 1.f / red[0]; }
}

// ---------------- H = alpha @ K ------------------------------------------------
// 16 rows x 64 cols per block, 128 threads, grid (2, 170) = 340 blocks.
// Inner loop per jj: 1 LDS.128 (K) + 2 broadcast LDS.32 (w) + 8 FMA.
__global__ void attn_h(const int* __restrict__ A, float* __restrict__ H) {
    __shared__ float4 Ksh[JT * 16];       // 64 jj x 64 cols (16KB)
    __shared__ float  wsh[JT][17];        // [jj][row], stride 17 conflict-free
    __shared__ float  pm[RPB], qm[RPB], mm[RPB], lm[RPB];
    int i0 = blockIdx.y * RPB;
    int cb = blockIdx.x * 16;             // float4 column base (0 or 16)
    int t  = threadIdx.x;
    if (t < RPB) {
        int gi = i0 + t;
        if (gi < N) { pm[t] = g_p[gi]; qm[t] = g_q[gi]; mm[t] = g_m[gi]; lm[t] = g_linv[gi]; }
        else        { pm[t] = 0.f; qm[t] = 0.f; mm[t] = 0.f; lm[t] = 0.f; }
    }
    int cg = t & 15;    // float4 col group within the 64-col half
    int rg = t >> 4;    // 0..7 -> rows 2rg, 2rg+1
    float4 acc0 = make_float4(0.f, 0.f, 0.f, 0.f);
    float4 acc1 = make_float4(0.f, 0.f, 0.f, 0.f);
    __syncthreads();
    for (int j0 = 0; j0 < N; j0 += JT) {
        // stage K tile half (coalesced float4)
#pragma unroll
        for (int l = 0; l < 8; l++) {
            int e = t + l * 128;
            int jj = e >> 4, c4 = e & 15;
            int gj = j0 + jj;
            Ksh[jj * 16 + c4] = (gj < N)
                ? ((const float4*)g_K)[(size_t)gj * 32 + cb + c4]
                : make_float4(0.f, 0.f, 0.f, 0.f);
        }
        // attention weights for this tile (coalesced A reads, jj fastest)
#pragma unroll
        for (int l = 0; l < 8; l++) {
            int e = t + l * 128;
            int jj = e & 63, r = e >> 6;
            int gi = i0 + r, gj = j0 + jj;
            float wv = 0.f;
            if (gi < N && gj < N && A[(size_t)gi * N + gj])
                wv = __expf(fabsf(pm[r] + qm[r] * g_k2[gj]) - mm[r]) * lm[r];
            wsh[jj][r] = wv;
        }
        __syncthreads();
#pragma unroll 8
        for (int jj = 0; jj < JT; jj++) {
            float4 kv = Ksh[jj * 16 + cg];
            float w0 = wsh[jj][2 * rg];
            float w1 = wsh[jj][2 * rg + 1];
            acc0.x += w0 * kv.x; acc0.y += w0 * kv.y; acc0.z += w0 * kv.z; acc0.w += w0 * kv.w;
            acc1.x += w1 * kv.x; acc1.y += w1 * kv.y; acc1.z += w1 * kv.z; acc1.w += w1 * kv.w;
        }
        __syncthreads();
    }
    int r0 = i0 + 2 * rg;
    if (r0 < N)     ((float4*)H)[(size_t)r0 * 32 + cb + cg]       = acc0;
    if (r0 + 1 < N) ((float4*)H)[(size_t)(r0 + 1) * 32 + cb + cg] = acc1;
}

// ---------------- launch -------------------------------------------------------
extern "C" void kernel_launch(void* const* d_in, const int* in_sizes, int n_in,
                              void* d_out, int out_size) {
    (void)in_sizes; (void)n_in; (void)out_size;
    const float* X    = (const float*)d_in[0];
    const int*   A    = (const int*)d_in[1];
    const float* U    = (const float*)d_in[2];
    const float* W    = (const float*)d_in[3];
    const float* a1   = (const float*)d_in[4];
    const float* a2   = (const float*)d_in[5];
    const float* lmbd = (const float*)d_in[6];
    float* H = (float*)d_out;

    gemm_k     <<<dim3(2, (N + 15) / 16), 128>>>(X, W);
    k1k2_kernel<<<(N + 7) / 8, 256>>>(a1, a2);
    colpart    <<<dim3((N + 255) / 256, NCH), 256>>>(U);
    colreduce  <<<(N + 255) / 256, 256>>>(lmbd);
    pq_kernel  <<<N, 256>>>(U);
    stats_kernel<<<N, 256>>>(A);
    attn_h     <<<dim3(2, (N + RPB - 1) / RPB), 128>>>(A, H);
}

// round 7
// speedup vs baseline: 1.8867x; 1.5900x over previous
#include <cuda_runtime.h>
#include <math.h>

#define N    2708
#define INC  1433
#define OC   128
#define NCH  32
#define RC   85      // ceil(N/NCH)
#define GZ   4       // gemm K-split
#define ARPB 19      // attn rows per block (143 blocks = 1 wave)
#define APAD 20
#define ATHR 160
#define AJT  32      // attn j-tile
#define NW4  677     // N/4

// ---------------- scratch (static device memory) -----------------------------
__device__ __align__(16) float g_Kp[GZ][N * OC];
__device__ __align__(16) float g_K[N * OC];
__device__ float g_k1[N], g_k2[N];
__device__ float g_part1[NCH * N], g_part2[NCH * N];
__device__ float g_s1[N], g_s2[N];
__device__ float g_p[N], g_q[N];
__device__ float g_m[N], g_linv[N];

__device__ __forceinline__ unsigned su32(const void* p) {
    return (unsigned)__cvta_generic_to_shared(p);
}
#define CP16(dst, src) asm volatile("cp.async.cg.shared.global [%0], [%1], 16;" :: "r"(dst), "l"(src) : "memory")
#define CPCOMMIT()     asm volatile("cp.async.commit_group;" ::: "memory")
#define CPWAIT0()      asm volatile("cp.async.wait_group 0;" ::: "memory")

// ---------------- K = X @ W^T, K-split over GZ chunks ------------------------
// BM=32, BN=64, BK=16, 128 threads, 4x4 thread tile, float4 LDS both sides.
__global__ void gemm_k(const float* __restrict__ X, const float* __restrict__ W) {
    __shared__ __align__(16) float Xs[16][36];
    __shared__ __align__(16) float Ws[16][68];
    int i0 = blockIdx.y * 32;
    int c0 = blockIdx.x * 64;
    int z  = blockIdx.z;
    int kb = (INC * z) / GZ;
    int ke = (INC * (z + 1)) / GZ;
    int t  = threadIdx.x;
    int tx = t & 15;      // cols 4tx..4tx+3
    int ty = t >> 4;      // rows 4ty..4ty+3
    float acc[4][4] = {};
    for (int kt = kb; kt < ke; kt += 16) {
#pragma unroll
        for (int l = 0; l < 4; l++) {
            int e = t + l * 128;
            int r = e >> 4, kk = e & 15;
            int gi = i0 + r, gk = kt + kk;
            Xs[kk][r] = (gi < N && gk < ke) ? X[(size_t)gi * INC + gk] : 0.f;
        }
#pragma unroll
        for (int l = 0; l < 8; l++) {
            int e = t + l * 128;
            int c = e >> 4, kk = e & 15;
            int gk = kt + kk;
            Ws[kk][c] = (gk < ke) ? W[(size_t)(c0 + c) * INC + gk] : 0.f;
        }
        __syncthreads();
#pragma unroll
        for (int kk = 0; kk < 16; kk++) {
            float4 a = *(const float4*)&Xs[kk][4 * ty];
            float4 b = *(const float4*)&Ws[kk][4 * tx];
            acc[0][0] += a.x * b.x; acc[0][1] += a.x * b.y; acc[0][2] += a.x * b.z; acc[0][3] += a.x * b.w;
            acc[1][0] += a.y * b.x; acc[1][1] += a.y * b.y; acc[1][2] += a.y * b.z; acc[1][3] += a.y * b.w;
            acc[2][0] += a.z * b.x; acc[2][1] += a.z * b.y; acc[2][2] += a.z * b.z; acc[2][3] += a.z * b.w;
            acc[3][0] += a.w * b.x; acc[3][1] += a.w * b.y; acc[3][2] += a.w * b.z; acc[3][3] += a.w * b.w;
        }
        __syncthreads();
    }
#pragma unroll
    for (int rr = 0; rr < 4; rr++) {
        int gi = i0 + 4 * ty + rr;
        if (gi < N) {
            float4 v = make_float4(acc[rr][0], acc[rr][1], acc[rr][2], acc[rr][3]);
            *(float4*)&g_Kp[z][(size_t)gi * OC + c0 + 4 * tx] = v;
        }
    }
}

// ---------------- fold GZ partials -> g_K, plus k1,k2 (one warp/row) --------
__global__ void fold_k1k2(const float* __restrict__ a1, const float* __restrict__ a2) {
    int w = threadIdx.x >> 5;
    int lane = threadIdx.x & 31;
    int i = blockIdx.x * 8 + w;
    if (i >= N) return;
    float d1 = 0.f, d2 = 0.f;
#pragma unroll
    for (int u = 0; u < 4; u++) {
        int c = lane + 32 * u;
        size_t idx = (size_t)i * OC + c;
        float kv = g_Kp[0][idx] + g_Kp[1][idx] + g_Kp[2][idx] + g_Kp[3][idx];
        g_K[idx] = kv;
        d1 += kv * a1[c];
        d2 += kv * a2[c];
    }
#pragma unroll
    for (int off = 16; off; off >>= 1) {
        d1 += __shfl_down_sync(0xffffffffu, d1, off);
        d2 += __shfl_down_sync(0xffffffffu, d2, off);
    }
    if (lane == 0) { g_k1[i] = d1; g_k2[i] = d2; }
}

// ---------------- column partials: t1 = U^T k1, t2 = U^T 1 -------------------
__global__ void colpart(const float* __restrict__ U) {
    int j  = blockIdx.x * 256 + threadIdx.x;
    int ch = blockIdx.y;
    if (j >= N) return;
    int ib = ch * RC;
    int ie = min(N, ib + RC);
    float a = 0.f, b = 0.f;
    for (int i = ib; i < ie; i++) {
        float u = U[(size_t)i * N + j];
        a += u * g_k1[i];
        b += u;
    }
    g_part1[ch * N + j] = a;
    g_part2[ch * N + j] = b;
}

// ---------------- s = lmbd * t ------------------------------------------------
__global__ void colreduce(const float* __restrict__ lmbd) {
    int j = blockIdx.x * 256 + threadIdx.x;
    if (j >= N) return;
    float a = 0.f, b = 0.f;
#pragma unroll
    for (int c = 0; c < NCH; c++) {
        a += g_part1[c * N + j];
        b += g_part2[c * N + j];
    }
    float l = lmbd[j];
    g_s1[j] = l * a;
    g_s2[j] = l * b;
}

// ---------------- p = U s1, q = U s2 ------------------------------------------
__global__ void pq_kernel(const float* __restrict__ U) {
    __shared__ float r1[256], r2[256];
    int i = blockIdx.x;
    int t = threadIdx.x;
    float a = 0.f, b = 0.f;
    const float4* Ur = (const float4*)(U + (size_t)i * N);
    for (int j4 = t; j4 < NW4; j4 += 256) {
        float4 u = Ur[j4];
        int j = 4 * j4;
        a += u.x * g_s1[j] + u.y * g_s1[j + 1] + u.z * g_s1[j + 2] + u.w * g_s1[j + 3];
        b += u.x * g_s2[j] + u.y * g_s2[j + 1] + u.z * g_s2[j + 2] + u.w * g_s2[j + 3];
    }
    r1[t] = a; r2[t] = b;
    __syncthreads();
    for (int s = 128; s; s >>= 1) {
        if (t < s) { r1[t] += r1[t + s]; r2[t] += r2[t + s]; }
        __syncthreads();
    }
    if (t == 0) { g_p[i] = r1[0]; g_q[i] = r2[0]; }
}

// ---------------- per-row masked softmax stats --------------------------------
__global__ void stats_kernel(const int* __restrict__ A) {
    __shared__ float red[256];
    int i = blockIdx.x, t = threadIdx.x;
    float pi = g_p[i], qi = g_q[i];
    const int* Arow = A + (size_t)i * N;
    float mx = -INFINITY;
    for (int j = t; j < N; j += 256)
        if (Arow[j]) mx = fmaxf(mx, fabsf(pi + qi * g_k2[j]));
    red[t] = mx;
    __syncthreads();
    for (int s = 128; s; s >>= 1) {
        if (t < s) red[t] = fmaxf(red[t], red[t + s]);
        __syncthreads();
    }
    float m = red[0];
    __syncthreads();
    float sum = 0.f;
    for (int j = t; j < N; j += 256)
        if (Arow[j]) sum += __expf(fabsf(pi + qi * g_k2[j]) - m);
    red[t] = sum;
    __syncthreads();
    for (int s = 128; s; s >>= 1) {
        if (t < s) red[t] += red[t + s];
        __syncthreads();
    }
    if (t == 0) { g_m[i] = m; g_linv[i] = 1.f / red[0]; }
}

// ---------------- H = alpha @ K -----------------------------------------------
// 19 rows x 128 cols per block, 143 blocks (1 wave, 1 block/SM), 160 threads.
// Thread tile 4 rows x 4 cols: per jj 1 LDS.128 (K) + 1 LDS.128 (w) + 16 FMA.
// A prefetched into registers one tile ahead; K tiles double-buffered via cp.async.
__global__ void attn_h(const int* __restrict__ A, float* __restrict__ H) {
    __shared__ __align__(16) float4 Ksh[2][AJT][32];   // 2 x 16KB
    __shared__ __align__(16) float  wsh[2][AJT][APAD]; // 2 x 2.5KB
    __shared__ float pm[APAD], qm[APAD], mm[APAD], lm[APAD];

    int i0 = blockIdx.x * ARPB;
    int t  = threadIdx.x;
    int cg = t & 31;     // float4 col group
    int rg = t >> 5;     // 0..4 -> rows 4rg..4rg+3
    const float4* Kf4 = (const float4*)g_K;

    if (t < APAD) {
        int gi = i0 + t;
        bool v = (t < ARPB && gi < N);
        pm[t] = v ? g_p[gi]    : 0.f;
        qm[t] = v ? g_q[gi]    : 0.f;
        mm[t] = v ? g_m[gi]    : 0.f;
        lm[t] = v ? g_linv[gi] : 0.f;
    }

    int ar[4];
    // prefetch A for tile 0
#pragma unroll
    for (int l = 0; l < 4; l++) {
        int e = t + l * ATHR;
        int jj = e & 31, r = e >> 5;
        int gi = i0 + r;
        ar[l] = (r < ARPB && gi < N && jj < N) ? A[(size_t)gi * N + jj] : 0;
    }
    // stage K tile 0 -> buf 0
#pragma unroll
    for (int l = 0; l < 7; l++) {
        int e = t + l * ATHR;
        if (e < AJT * 32) {
            int jj = e >> 5, c4 = e & 31;
            if (jj < N) CP16(su32(&Ksh[0][jj][c4]), &Kf4[(size_t)jj * 32 + c4]);
            else        Ksh[0][jj][c4] = make_float4(0.f, 0.f, 0.f, 0.f);
        }
    }
    CPCOMMIT();
    __syncthreads();   // pm/qm/mm/lm visible
    // build wsh tile 0 (consumes ar), then prefetch A tile 1
#pragma unroll
    for (int l = 0; l < 4; l++) {
        int e = t + l * ATHR;
        int jj = e & 31, r = e >> 5;
        float wv = 0.f;
        if (ar[l]) wv = __expf(fabsf(pm[r] + qm[r] * g_k2[jj]) - mm[r]) * lm[r];
        wsh[0][jj][r] = wv;
    }
#pragma unroll
    for (int l = 0; l < 4; l++) {
        int e = t + l * ATHR;
        int jj = e & 31, r = e >> 5;
        int gi = i0 + r, gj = AJT + jj;
        ar[l] = (r < ARPB && gi < N && gj < N) ? A[(size_t)gi * N + gj] : 0;
    }
    CPWAIT0();
    __syncthreads();

    float4 acc[4];
#pragma unroll
    for (int rr = 0; rr < 4; rr++) acc[rr] = make_float4(0.f, 0.f, 0.f, 0.f);

    int buf = 0;
    for (int j0 = 0; j0 < N; j0 += AJT) {
        int jn = j0 + AJT;
        if (jn < N) {
            int nb = buf ^ 1;
            // stage next K tile (async, overlaps FMA)
#pragma unroll
            for (int l = 0; l < 7; l++) {
                int e = t + l * ATHR;
                if (e < AJT * 32) {
                    int jj = e >> 5, c4 = e & 31;
                    int gj = jn + jj;
                    if (gj < N) CP16(su32(&Ksh[nb][jj][c4]), &Kf4[(size_t)gj * 32 + c4]);
                    else        Ksh[nb][jj][c4] = make_float4(0.f, 0.f, 0.f, 0.f);
                }
            }
            CPCOMMIT();
            // build next w tile from prefetched A regs
#pragma unroll
            for (int l = 0; l < 4; l++) {
                int e = t + l * ATHR;
                int jj = e & 31, r = e >> 5;
                int gj = jn + jj;
                float wv = 0.f;
                if (ar[l]) wv = __expf(fabsf(pm[r] + qm[r] * g_k2[gj]) - mm[r]) * lm[r];
                wsh[nb][jj][r] = wv;
            }
            // prefetch A for tile after next
            if (jn + AJT < N) {
#pragma unroll
                for (int l = 0; l < 4; l++) {
                    int e = t + l * ATHR;
                    int jj = e & 31, r = e >> 5;
                    int gi = i0 + r, gj = jn + AJT + jj;
                    ar[l] = (r < ARPB && gi < N && gj < N) ? A[(size_t)gi * N + gj] : 0;
                }
            }
        }
        // FMA on current buffer
#pragma unroll 8
        for (int jj = 0; jj < AJT; jj++) {
            float4 kv = Ksh[buf][jj][cg];
            float4 wv = *(const float4*)&wsh[buf][jj][4 * rg];
            acc[0].x += wv.x * kv.x; acc[0].y += wv.x * kv.y; acc[0].z += wv.x * kv.z; acc[0].w += wv.x * kv.w;
            acc[1].x += wv.y * kv.x; acc[1].y += wv.y * kv.y; acc[1].z += wv.y * kv.z; acc[1].w += wv.y * kv.w;
            acc[2].x += wv.z * kv.x; acc[2].y += wv.z * kv.y; acc[2].z += wv.z * kv.z; acc[2].w += wv.z * kv.w;
            acc[3].x += wv.w * kv.x; acc[3].y += wv.w * kv.y; acc[3].z += wv.w * kv.z; acc[3].w += wv.w * kv.w;
        }
        if (jn < N) CPWAIT0();
        __syncthreads();
        buf ^= 1;
    }

#pragma unroll
    for (int rr = 0; rr < 4; rr++) {
        int rl = 4 * rg + rr;
        int gi = i0 + rl;
        if (rl < ARPB && gi < N)
            ((float4*)H)[(size_t)gi * 32 + cg] = acc[rr];
    }
}

// ---------------- launch -------------------------------------------------------
extern "C" void kernel_launch(void* const* d_in, const int* in_sizes, int n_in,
                              void* d_out, int out_size) {
    (void)in_sizes; (void)n_in; (void)out_size;
    const float* X    = (const float*)d_in[0];
    const int*   A    = (const int*)d_in[1];
    const float* U    = (const float*)d_in[2];
    const float* W    = (const float*)d_in[3];
    const float* a1   = (const float*)d_in[4];
    const float* a2   = (const float*)d_in[5];
    const float* lmbd = (const float*)d_in[6];
    float* H = (float*)d_out;

    gemm_k     <<<dim3(2, (N + 31) / 32, GZ), 128>>>(X, W);
    fold_k1k2  <<<(N + 7) / 8, 256>>>(a1, a2);
    colpart    <<<dim3((N + 255) / 256, NCH), 256>>>(U);
    colreduce  <<<(N + 255) / 256, 256>>>(lmbd);
    pq_kernel  <<<N, 256>>>(U);
    stats_kernel<<<N, 256>>>(A);
    attn_h     <<<(N + ARPB - 1) / ARPB, ATHR>>>(A, H);
}

// round 8
// speedup vs baseline: 1.9670x; 1.0426x over previous
#include <cuda_runtime.h>
#include <math.h>

#define N    2708
#define INC  1433
#define OC   128
#define NCH  32
#define RC   85      // ceil(N/NCH)
#define GZ   4       // gemm K-split
#define ARPB 19      // attn rows per block (143 blocks = 1 wave)
#define ATHR 160
#define AJT  32      // attn j-tile
#define NWRD 85      // ceil(N/32) bitmask words per row
#define NW4  677     // N/4

// ---------------- scratch (static device memory) -----------------------------
__device__ __align__(16) float g_Kp[GZ][N * OC];
__device__ __align__(16) float g_K[N * OC];
__device__ float g_k1[N], g_k2[N];
__device__ float g_part1[NCH * N], g_part2[NCH * N];
__device__ float g_s1[N], g_s2[N];
__device__ float g_p[N], g_q[N];

__device__ __forceinline__ unsigned su32(const void* p) {
    return (unsigned)__cvta_generic_to_shared(p);
}
#define CP16(dst, src) asm volatile("cp.async.cg.shared.global [%0], [%1], 16;" :: "r"(dst), "l"(src) : "memory")
#define CPCOMMIT()     asm volatile("cp.async.commit_group;" ::: "memory")
#define CPWAIT0()      asm volatile("cp.async.wait_group 0;" ::: "memory")

// ---------------- K = X @ W^T, K-split, register-pipelined --------------------
// BM=32, BN=64, BK=16, 128 threads, 4x4 thread tile, float4 LDS both sides.
__global__ void gemm_k(const float* __restrict__ X, const float* __restrict__ W) {
    __shared__ __align__(16) float Xs[16][36];
    __shared__ __align__(16) float Ws[16][68];
    int i0 = blockIdx.y * 32;
    int c0 = blockIdx.x * 64;
    int z  = blockIdx.z;
    int kb = (INC * z) / GZ;
    int ke = (INC * (z + 1)) / GZ;
    int t  = threadIdx.x;
    int tx = t & 15;      // cols 4tx..4tx+3
    int ty = t >> 4;      // rows 4ty..4ty+3
    float acc[4][4] = {};
    float xr[4], wr[8];

    // preload first tile into registers
#pragma unroll
    for (int l = 0; l < 4; l++) {
        int e = t + l * 128;
        int r = e >> 4, kk = e & 15;
        int gi = i0 + r, gk = kb + kk;
        xr[l] = (gi < N && gk < ke) ? X[(size_t)gi * INC + gk] : 0.f;
    }
#pragma unroll
    for (int l = 0; l < 8; l++) {
        int e = t + l * 128;
        int c = e >> 4, kk = e & 15;
        int gk = kb + kk;
        wr[l] = (gk < ke) ? W[(size_t)(c0 + c) * INC + gk] : 0.f;
    }

    for (int kt = kb; kt < ke; kt += 16) {
        // commit registers to smem
#pragma unroll
        for (int l = 0; l < 4; l++) {
            int e = t + l * 128;
            Xs[e & 15][e >> 4] = xr[l];
        }
#pragma unroll
        for (int l = 0; l < 8; l++) {
            int e = t + l * 128;
            Ws[e & 15][e >> 4] = wr[l];
        }
        __syncthreads();
        // prefetch next tile (overlaps FMA below)
        int ktn = kt + 16;
        if (ktn < ke) {
#pragma unroll
            for (int l = 0; l < 4; l++) {
                int e = t + l * 128;
                int r = e >> 4, kk = e & 15;
                int gi = i0 + r, gk = ktn + kk;
                xr[l] = (gi < N && gk < ke) ? X[(size_t)gi * INC + gk] : 0.f;
            }
#pragma unroll
            for (int l = 0; l < 8; l++) {
                int e = t + l * 128;
                int c = e >> 4, kk = e & 15;
                int gk = ktn + kk;
                wr[l] = (gk < ke) ? W[(size_t)(c0 + c) * INC + gk] : 0.f;
            }
        }
#pragma unroll
        for (int kk = 0; kk < 16; kk++) {
            float4 a = *(const float4*)&Xs[kk][4 * ty];
            float4 b = *(const float4*)&Ws[kk][4 * tx];
            acc[0][0] += a.x * b.x; acc[0][1] += a.x * b.y; acc[0][2] += a.x * b.z; acc[0][3] += a.x * b.w;
            acc[1][0] += a.y * b.x; acc[1][1] += a.y * b.y; acc[1][2] += a.y * b.z; acc[1][3] += a.y * b.w;
            acc[2][0] += a.z * b.x; acc[2][1] += a.z * b.y; acc[2][2] += a.z * b.z; acc[2][3] += a.z * b.w;
            acc[3][0] += a.w * b.x; acc[3][1] += a.w * b.y; acc[3][2] += a.w * b.z; acc[3][3] += a.w * b.w;
        }
        __syncthreads();
    }
#pragma unroll
    for (int rr = 0; rr < 4; rr++) {
        int gi = i0 + 4 * ty + rr;
        if (gi < N) {
            float4 v = make_float4(acc[rr][0], acc[rr][1], acc[rr][2], acc[rr][3]);
            *(float4*)&g_Kp[z][(size_t)gi * OC + c0 + 4 * tx] = v;
        }
    }
}

// ---------------- fold GZ partials -> g_K, plus k1,k2 (one warp/row) ---------
__global__ void fold_k1k2(const float* __restrict__ a1, const float* __restrict__ a2) {
    int w = threadIdx.x >> 5;
    int lane = threadIdx.x & 31;
    int i = blockIdx.x * 8 + w;
    if (i >= N) return;
    float d1 = 0.f, d2 = 0.f;
#pragma unroll
    for (int u = 0; u < 4; u++) {
        int c = lane + 32 * u;
        size_t idx = (size_t)i * OC + c;
        float kv = g_Kp[0][idx] + g_Kp[1][idx] + g_Kp[2][idx] + g_Kp[3][idx];
        g_K[idx] = kv;
        d1 += kv * a1[c];
        d2 += kv * a2[c];
    }
#pragma unroll
    for (int off = 16; off; off >>= 1) {
        d1 += __shfl_down_sync(0xffffffffu, d1, off);
        d2 += __shfl_down_sync(0xffffffffu, d2, off);
    }
    if (lane == 0) { g_k1[i] = d1; g_k2[i] = d2; }
}

// ---------------- column partials: t1 = U^T k1, t2 = U^T 1 --------------------
__global__ void colpart(const float* __restrict__ U) {
    int j  = blockIdx.x * 256 + threadIdx.x;
    int ch = blockIdx.y;
    if (j >= N) return;
    int ib = ch * RC;
    int ie = min(N, ib + RC);
    float a = 0.f, b = 0.f;
    for (int i = ib; i < ie; i++) {
        float u = U[(size_t)i * N + j];
        a += u * g_k1[i];
        b += u;
    }
    g_part1[ch * N + j] = a;
    g_part2[ch * N + j] = b;
}

// ---------------- s = lmbd * t -------------------------------------------------
__global__ void colreduce(const float* __restrict__ lmbd) {
    int j = blockIdx.x * 256 + threadIdx.x;
    if (j >= N) return;
    float a = 0.f, b = 0.f;
#pragma unroll
    for (int c = 0; c < NCH; c++) {
        a += g_part1[c * N + j];
        b += g_part2[c * N + j];
    }
    float l = lmbd[j];
    g_s1[j] = l * a;
    g_s2[j] = l * b;
}

// ---------------- p = U s1, q = U s2 -------------------------------------------
__global__ void pq_kernel(const float* __restrict__ U) {
    __shared__ float r1[256], r2[256];
    int i = blockIdx.x;
    int t = threadIdx.x;
    float a = 0.f, b = 0.f;
    const float4* Ur = (const float4*)(U + (size_t)i * N);
    for (int j4 = t; j4 < NW4; j4 += 256) {
        float4 u = Ur[j4];
        int j = 4 * j4;
        a += u.x * g_s1[j] + u.y * g_s1[j + 1] + u.z * g_s1[j + 2] + u.w * g_s1[j + 3];
        b += u.x * g_s2[j] + u.y * g_s2[j + 1] + u.z * g_s2[j + 2] + u.w * g_s2[j + 3];
    }
    r1[t] = a; r2[t] = b;
    __syncthreads();
    for (int s = 128; s; s >>= 1) {
        if (t < s) { r1[t] += r1[t + s]; r2[t] += r2[t + s]; }
        __syncthreads();
    }
    if (t == 0) { g_p[i] = r1[0]; g_q[i] = r2[0]; }
}

// ---------------- fused masked-softmax + H = alpha @ K -------------------------
// 19 rows x 128 cols per block, 143 blocks (one wave), 160 threads.
// Phase 1: read A once -> smem bitmask + per-row masked max (ALU only).
// Main loop: w = exp(x - m) from bitmask; accumulate H AND denominator l.
// Epilogue: scale accumulators by 1/l.  (stats kernel eliminated)
__global__ void attn_h(const int* __restrict__ A, float* __restrict__ H) {
    __shared__ __align__(16) float4   Ksh[2][AJT][32];     // 32 KB
    __shared__ __align__(16) float    wsh[2][AJT][20];     // 5 KB
    __shared__ unsigned msk[20][NWRD];                     // 6.8 KB
    __shared__ int      mrowi[20];
    __shared__ float    pm[20], qm[20], mmf[20], lsum[20];

    int i0 = blockIdx.x * ARPB;
    int t  = threadIdx.x;
    int lane = t & 31;
    int rg   = t >> 5;        // warp 0..4
    const float4* Kf4 = (const float4*)g_K;

    // kick off K tile 0 immediately
#pragma unroll
    for (int l = 0; l < 7; l++) {
        int e = t + l * ATHR;
        if (e < AJT * 32) {
            int jj = e >> 5, c4 = e & 31;
            CP16(su32(&Ksh[0][jj][c4]), &Kf4[(size_t)jj * 32 + c4]);
        }
    }
    CPCOMMIT();

    if (t < 20) {
        int gi = i0 + t;
        bool v = (t < ARPB && gi < N);
        pm[t] = v ? g_p[gi] : 0.f;
        qm[t] = v ? g_q[gi] : 0.f;
        mrowi[t] = 0;
        lsum[t] = 0.f;
    }
    __syncthreads();

    // ---------- Phase 1: bitmask + masked row max (no exp) -------------------
    {
        int tr = t >> 3;          // row 0..19
        int l8 = t & 7;
        int gi = i0 + tr;
        if (tr < ARPB && gi < N) {
            float pr = pm[tr], qr = qm[tr];
            const int* Arow = A + (size_t)gi * N;
            float mloc = 0.f;
            for (int w = l8; w < NWRD; w += 8) {
                unsigned bits = 0;
                int jb = w * 32;
                const int4* Ap = (const int4*)(Arow + jb);
#pragma unroll
                for (int q4 = 0; q4 < 8; q4++) {
                    int j = jb + 4 * q4;
                    if (j >= N) break;
                    int4 av = Ap[q4];
#define PROC(v, jj_)                                                        \
                    if ((jj_) < N && (v)) {                                 \
                        bits |= 1u << ((jj_) - jb);                         \
                        float x = fabsf(pr + qr * __ldg(&g_k2[jj_]));       \
                        mloc = fmaxf(mloc, x);                              \
                    }
                    PROC(av.x, j + 0)
                    PROC(av.y, j + 1)
                    PROC(av.z, j + 2)
                    PROC(av.w, j + 3)
#undef PROC
                }
                msk[tr][w] = bits;
            }
            atomicMax(&mrowi[tr], __float_as_int(mloc));   // mloc >= 0: int order ok
        } else {
            for (int w = l8; w < NWRD; w += 8) msk[tr][w] = 0;
        }
    }
    __syncthreads();
    if (t < 20) mmf[t] = __int_as_float(mrowi[t]);
    __syncthreads();

    // ---------- build w tile 0 (rows rg+5l, col jj=lane) ----------------------
    float wsum[4] = {0.f, 0.f, 0.f, 0.f};
#pragma unroll
    for (int l = 0; l < 4; l++) {
        int r = rg + 5 * l;
        float wv = 0.f;
        if ((msk[r][lane >> 5 /*0*/ + 0] >> lane) & 1u)    // tile0: gj = lane, word 0
            wv = __expf(fabsf(pm[r] + qm[r] * __ldg(&g_k2[lane])) - mmf[r]);
        wsh[0][lane][r] = wv;
        wsum[l] += wv;
    }
    CPWAIT0();
    __syncthreads();

    float4 acc[4];
#pragma unroll
    for (int rr = 0; rr < 4; rr++) acc[rr] = make_float4(0.f, 0.f, 0.f, 0.f);

    int buf = 0;
    for (int j0 = 0; j0 < N; j0 += AJT) {
        int jn = j0 + AJT;
        if (jn < N) {
            int nb = buf ^ 1;
            // stage next K tile (async)
#pragma unroll
            for (int l = 0; l < 7; l++) {
                int e = t + l * ATHR;
                if (e < AJT * 32) {
                    int jj = e >> 5, c4 = e & 31;
                    int gj = jn + jj;
                    if (gj < N) CP16(su32(&Ksh[nb][jj][c4]), &Kf4[(size_t)gj * 32 + c4]);
                    else        Ksh[nb][jj][c4] = make_float4(0.f, 0.f, 0.f, 0.f);
                }
            }
            CPCOMMIT();
            // build next w tile from bitmask
            int gj = jn + lane;
            int wrd = gj >> 5;                    // same word for whole warp (aligned)
            unsigned bit = 1u << (gj & 31);
            float k2v = (gj < N) ? __ldg(&g_k2[gj]) : 0.f;
#pragma unroll
            for (int l = 0; l < 4; l++) {
                int r = rg + 5 * l;
                float wv = 0.f;
                if (gj < N && (msk[r][wrd] & bit))
                    wv = __expf(fabsf(pm[r] + qm[r] * k2v) - mmf[r]);
                wsh[nb][lane][r] = wv;
                wsum[l] += wv;
            }
        }
        // FMA on current buffer
#pragma unroll 8
        for (int jj = 0; jj < AJT; jj++) {
            float4 kv = Ksh[buf][jj][lane];
            float4 wv = *(const float4*)&wsh[buf][jj][4 * rg];
            acc[0].x += wv.x * kv.x; acc[0].y += wv.x * kv.y; acc[0].z += wv.x * kv.z; acc[0].w += wv.x * kv.w;
            acc[1].x += wv.y * kv.x; acc[1].y += wv.y * kv.y; acc[1].z += wv.y * kv.z; acc[1].w += wv.y * kv.w;
            acc[2].x += wv.z * kv.x; acc[2].y += wv.z * kv.y; acc[2].z += wv.z * kv.z; acc[2].w += wv.z * kv.w;
            acc[3].x += wv.w * kv.x; acc[3].y += wv.w * kv.y; acc[3].z += wv.w * kv.z; acc[3].w += wv.w * kv.w;
        }
        if (jn < N) CPWAIT0();
        __syncthreads();
        buf ^= 1;
    }

    // ---------- epilogue: denominators, scale, store --------------------------
#pragma unroll
    for (int l = 0; l < 4; l++) {
#pragma unroll
        for (int off = 16; off; off >>= 1)
            wsum[l] += __shfl_xor_sync(0xffffffffu, wsum[l], off);
        if (lane == 0) lsum[rg + 5 * l] = wsum[l];
    }
    __syncthreads();
#pragma unroll
    for (int rr = 0; rr < 4; rr++) {
        int rl = 4 * rg + rr;
        int gi = i0 + rl;
        if (rl < ARPB && gi < N) {
            float ls = lsum[rl];
            float s = (ls > 0.f) ? 1.f / ls : 0.f;
            float4 v = acc[rr];
            v.x *= s; v.y *= s; v.z *= s; v.w *= s;
            ((float4*)H)[(size_t)gi * 32 + lane] = v;
        }
    }
}

// ---------------- launch --------------------------------------------------------
extern "C" void kernel_launch(void* const* d_in, const int* in_sizes, int n_in,
                              void* d_out, int out_size) {
    (void)in_sizes; (void)n_in; (void)out_size;
    const float* X    = (const float*)d_in[0];
    const int*   A    = (const int*)d_in[1];
    const float* U    = (const float*)d_in[2];
    const float* W    = (const float*)d_in[3];
    const float* a1   = (const float*)d_in[4];
    const float* a2   = (const float*)d_in[5];
    const float* lmbd = (const float*)d_in[6];
    float* H = (float*)d_out;

    gemm_k    <<<dim3(2, (N + 31) / 32, GZ), 128>>>(X, W);
    fold_k1k2 <<<(N + 7) / 8, 256>>>(a1, a2);
    colpart   <<<dim3((N + 255) / 256, NCH), 256>>>(U);
    colreduce <<<(N + 255) / 256, 256>>>(lmbd);
    pq_kernel <<<N, 256>>>(U);
    attn_h    <<<(N + ARPB - 1) / ARPB, ATHR>>>(A, H);
}